// round 9
// baseline (speedup 1.0000x reference)
#include <cuda_runtime.h>
#include <cuda_bf16.h>
#include <math.h>
#include <stdint.h>

#define HIDDEN 1024
#define HEADS  16
#define HD     64
#define BATCH  4
#define SEQ    2048
#define MTOT   (BATCH * SEQ)   // 8192

// ---------------- scratch (device globals; no allocs allowed) --------------
__device__ __nv_bfloat16 g_a_hi[MTOT * HIDDEN];
__device__ __nv_bfloat16 g_a_lo[MTOT * HIDDEN];
__device__ __nv_bfloat16 g_wq_hi[3 * HIDDEN * HIDDEN];
__device__ __nv_bfloat16 g_wq_lo[3 * HIDDEN * HIDDEN];
__device__ __nv_bfloat16 g_wo_hi[HIDDEN * HIDDEN];
__device__ __nv_bfloat16 g_wo_lo[HIDDEN * HIDDEN];
__device__ __nv_bfloat16 g_qh[BATCH * HEADS * SEQ * HD];
__device__ __nv_bfloat16 g_ql[BATCH * HEADS * SEQ * HD];
__device__ __nv_bfloat16 g_kh[BATCH * HEADS * SEQ * HD];
__device__ __nv_bfloat16 g_kl[BATCH * HEADS * SEQ * HD];
__device__ __nv_bfloat16 g_vth[BATCH * HEADS * HD * SEQ];
__device__ __nv_bfloat16 g_vtl[BATCH * HEADS * HD * SEQ];

// ---------------- async-copy / ldmatrix helpers -----------------------------
__device__ __forceinline__ void cp_async16(uint32_t saddr, const void* gptr) {
    asm volatile("cp.async.ca.shared.global [%0], [%1], 16;"
                 :: "r"(saddr), "l"(gptr));
}
#define CP_COMMIT()  asm volatile("cp.async.commit_group;" ::: "memory")
#define CP_WAIT(n)   asm volatile("cp.async.wait_group %0;" :: "n"(n) : "memory")

__device__ __forceinline__ void ldsm4(uint32_t* r, uint32_t addr) {
    asm volatile("ldmatrix.sync.aligned.m8n8.x4.shared.b16 {%0,%1,%2,%3}, [%4];"
                 : "=r"(r[0]), "=r"(r[1]), "=r"(r[2]), "=r"(r[3]) : "r"(addr));
}

// ---------------------------------------------------------------------------
__global__ __launch_bounds__(256) void split_kernel(
    const float* __restrict__ src, __nv_bfloat16* __restrict__ hi,
    __nv_bfloat16* __restrict__ lo, int n4)
{
    int i = blockIdx.x * blockDim.x + threadIdx.x;
    if (i >= n4) return;
    float4 v = ((const float4*)src)[i];
    float xs[4] = {v.x, v.y, v.z, v.w};
    __nv_bfloat16 h[4], l[4];
    #pragma unroll
    for (int j = 0; j < 4; j++) {
        h[j] = __float2bfloat16_rn(xs[j]);
        l[j] = __float2bfloat16_rn(xs[j] - __bfloat162float(h[j]));
    }
    ((__nv_bfloat162*)hi)[2 * i]     = __nv_bfloat162(h[0], h[1]);
    ((__nv_bfloat162*)hi)[2 * i + 1] = __nv_bfloat162(h[2], h[3]);
    ((__nv_bfloat162*)lo)[2 * i]     = __nv_bfloat162(l[0], l[1]);
    ((__nv_bfloat162*)lo)[2 * i + 1] = __nv_bfloat162(l[2], l[3]);
}

__global__ void tsplit_kernel(const float* __restrict__ W,
                              __nv_bfloat16* __restrict__ hi,
                              __nv_bfloat16* __restrict__ lo, int K, int N)
{
    __shared__ float t[32][33];
    int n0 = blockIdx.x * 32, k0 = blockIdx.y * 32;
    for (int r = threadIdx.y; r < 32; r += 8)
        t[r][threadIdx.x] = W[(size_t)(k0 + r) * N + n0 + threadIdx.x];
    __syncthreads();
    for (int r = threadIdx.y; r < 32; r += 8) {
        float x = t[threadIdx.x][r];
        __nv_bfloat16 h = __float2bfloat16_rn(x);
        __nv_bfloat16 l = __float2bfloat16_rn(x - __bfloat162float(h));
        size_t o = (size_t)(n0 + r) * K + k0 + threadIdx.x;
        hi[o] = h;
        lo[o] = l;
    }
}

// ---------------------------------------------------------------------------
__device__ __forceinline__ void mma16816(float* c, const uint32_t* a, const uint32_t* b)
{
    asm volatile(
        "mma.sync.aligned.m16n8k16.row.col.f32.bf16.bf16.f32 "
        "{%0,%1,%2,%3}, {%4,%5,%6,%7}, {%8,%9}, {%0,%1,%2,%3};"
        : "+f"(c[0]), "+f"(c[1]), "+f"(c[2]), "+f"(c[3])
        : "r"(a[0]), "r"(a[1]), "r"(a[2]), "r"(a[3]), "r"(b[0]), "r"(b[1]));
}

__device__ __forceinline__ __nv_bfloat162 split_pack(float x, float y,
                                                     __nv_bfloat162* lo)
{
    __nv_bfloat16 hx = __float2bfloat16_rn(x);
    __nv_bfloat16 hy = __float2bfloat16_rn(y);
    *lo = __nv_bfloat162(__float2bfloat16_rn(x - __bfloat162float(hx)),
                         __float2bfloat16_rn(y - __bfloat162float(hy)));
    return __nv_bfloat162(hx, hy);
}

// ---------------------------------------------------------------------------
// HMMA GEMM: CTA 128x128, 4 warps (2x2), warp tile 64x64.
// cp.async 2-stage + ldmatrix. 2 CTAs/SM.
// ---------------------------------------------------------------------------
#define SPAD 40
#define GST  40960
#define GEMM_SMEM (2 * GST)

__global__ __launch_bounds__(128, 2) void hmma_gemm(
    const __nv_bfloat16* __restrict__ Ahi, const __nv_bfloat16* __restrict__ Alo,
    const __nv_bfloat16* __restrict__ Bhi, const __nv_bfloat16* __restrict__ Blo,
    const float* __restrict__ bias, float* __restrict__ C,
    __nv_bfloat16* __restrict__ qh, __nv_bfloat16* __restrict__ ql,
    __nv_bfloat16* __restrict__ kh, __nv_bfloat16* __restrict__ kl,
    __nv_bfloat16* __restrict__ vth, __nv_bfloat16* __restrict__ vtl,
    int M, int N, int K, int mode)
{
    extern __shared__ char smem[];
    const uint32_t sbase = (uint32_t)__cvta_generic_to_shared(smem);

    const int tid  = threadIdx.x;
    const int wid  = tid >> 5;
    const int lane = tid & 31;
    const int grp  = lane >> 2;
    const int tig  = lane & 3;
    const int wm   = wid & 1;          // 2 warps over M (64 rows each)
    const int wn   = wid >> 1;         // 2 warps over N (64 cols each)
    const int bm   = blockIdx.y * 128;
    const int bn   = blockIdx.x * 128;
    const int NT   = K / 32;

    const int mat = lane >> 3, lr = lane & 7;
    const int a_row = (mat & 1) * 8 + lr;
    const int a_col = (mat >> 1) * 8;
    const int b_jo  = mat >> 1;
    const int b_col = (mat & 1) * 8;

    float c[4][8][4];
    #pragma unroll
    for (int i = 0; i < 4; i++)
        #pragma unroll
        for (int j = 0; j < 8; j++)
            #pragma unroll
            for (int p = 0; p < 4; p++) c[i][j][p] = 0.f;

    auto issue_tile = [&](int kt, int stage) {
        const int k0 = kt * 32;
        const uint32_t st = sbase + stage * GST;
        #pragma unroll
        for (int u = 0; u < 4; u++) {
            int g = tid + u * 128;          // 0..511
            int r = g >> 2, ch = g & 3;
            uint32_t so = (uint32_t)(r * SPAD + ch * 8) * 2;
            size_t ga = (size_t)(bm + r) * K + k0 + ch * 8;
            size_t gb = (size_t)(bn + r) * K + k0 + ch * 8;
            cp_async16(st + so,         Ahi + ga);
            cp_async16(st + 10240 + so, Alo + ga);
            cp_async16(st + 20480 + so, Bhi + gb);
            cp_async16(st + 30720 + so, Blo + gb);
        }
        CP_COMMIT();
    };

    issue_tile(0, 0);

    for (int kt = 0; kt < NT; kt++) {
        if (kt + 1 < NT) {
            issue_tile(kt + 1, (kt + 1) & 1);
            CP_WAIT(1);
        } else {
            CP_WAIT(0);
        }
        __syncthreads();

        const uint32_t st = sbase + (kt & 1) * GST;

        #pragma unroll
        for (int ks = 0; ks < 2; ks++) {
            const int kk = ks * 16;
            uint32_t ah[4][4], al[4][4], bh[4][4], bl[4][4];
            #pragma unroll
            for (int i = 0; i < 4; i++) {
                uint32_t ad = st + (uint32_t)((wm * 64 + i * 16 + a_row) * SPAD + kk + a_col) * 2;
                ldsm4(ah[i], ad);
                ldsm4(al[i], ad + 10240);
            }
            #pragma unroll
            for (int p = 0; p < 4; p++) {
                uint32_t bd = st + 20480 +
                    (uint32_t)((wn * 64 + (p * 2 + b_jo) * 8 + lr) * SPAD + kk + b_col) * 2;
                ldsm4(bh[p], bd);
                ldsm4(bl[p], bd + 10240);
            }
            // pass 1: Ahi * Bhi
            #pragma unroll
            for (int i = 0; i < 4; i++)
                #pragma unroll
                for (int j = 0; j < 8; j++)
                    mma16816(c[i][j], ah[i], &bh[j >> 1][(j & 1) * 2]);
            // pass 2: Ahi * Blo
            #pragma unroll
            for (int i = 0; i < 4; i++)
                #pragma unroll
                for (int j = 0; j < 8; j++)
                    mma16816(c[i][j], ah[i], &bl[j >> 1][(j & 1) * 2]);
            // pass 3: Alo * Bhi
            #pragma unroll
            for (int i = 0; i < 4; i++)
                #pragma unroll
                for (int j = 0; j < 8; j++)
                    mma16816(c[i][j], al[i], &bh[j >> 1][(j & 1) * 2]);
        }
        __syncthreads();
    }

    #pragma unroll
    for (int i = 0; i < 4; i++) {
        #pragma unroll
        for (int j = 0; j < 8; j++) {
            int n0 = bn + wn * 64 + j * 8 + tig * 2;
            float2 bv = *(const float2*)(bias + n0);
            #pragma unroll
            for (int half = 0; half < 2; half++) {
                int m = bm + wm * 64 + i * 16 + grp + half * 8;
                float rx = c[i][j][half * 2 + 0] + bv.x;
                float ry = c[i][j][half * 2 + 1] + bv.y;
                if (mode == 0) {
                    *(float2*)(C + (size_t)m * N + n0) = make_float2(rx, ry);
                } else {
                    int sel = n0 >> 10, rem = n0 & 1023;
                    int h = rem >> 6, hd0 = rem & 63;
                    int b = m >> 11, s = m & 2047;
                    size_t bh_ = (size_t)b * HEADS + h;
                    if (sel == 0) {
                        __nv_bfloat162 lo2;
                        __nv_bfloat162 hi2 = split_pack(rx * 0.125f, ry * 0.125f, &lo2);
                        size_t off = (bh_ * SEQ + s) * HD + hd0;
                        *(__nv_bfloat162*)(qh + off) = hi2;
                        *(__nv_bfloat162*)(ql + off) = lo2;
                    } else if (sel == 1) {
                        __nv_bfloat162 lo2;
                        __nv_bfloat162 hi2 = split_pack(rx, ry, &lo2);
                        size_t off = (bh_ * SEQ + s) * HD + hd0;
                        *(__nv_bfloat162*)(kh + off) = hi2;
                        *(__nv_bfloat162*)(kl + off) = lo2;
                    } else {
                        __nv_bfloat162 lo2;
                        __nv_bfloat162 hi2 = split_pack(rx, ry, &lo2);
                        size_t o0 = (bh_ * HD + hd0) * SEQ + s;
                        size_t o1 = (bh_ * HD + hd0 + 1) * SEQ + s;
                        vth[o0] = hi2.x; vth[o1] = hi2.y;
                        vtl[o0] = lo2.x; vtl[o1] = lo2.y;
                    }
                }
            }
        }
    }
}

// ---------------------------------------------------------------------------
// HMMA flash attention: CTA 128 q-rows, 4 warps x 32 q-rows (2 m16 tiles),
// 64-key tiles, cp.async 2-stage + ldmatrix, 2 CTAs/SM. Each K/V fragment
// feeds 12 MMAs (2 m-tiles x 2 j x 3 passes).
// ---------------------------------------------------------------------------
#define KPITCH 72
#define AST    36864
#define ATTN_SMEM (2 * AST)

__global__ __launch_bounds__(128, 2) void attn_hmma(
    const __nv_bfloat16* __restrict__ qh, const __nv_bfloat16* __restrict__ ql,
    const __nv_bfloat16* __restrict__ kh, const __nv_bfloat16* __restrict__ kl,
    const __nv_bfloat16* __restrict__ vth, const __nv_bfloat16* __restrict__ vtl,
    __nv_bfloat16* __restrict__ Ohi, __nv_bfloat16* __restrict__ Olo)
{
    extern __shared__ char smem[];
    const uint32_t sbase = (uint32_t)__cvta_generic_to_shared(smem);

    const int tid  = threadIdx.x;
    const int wid  = tid >> 5;          // 0..3, each owns 32 q-rows
    const int lane = tid & 31;
    const int grp  = lane >> 2;
    const int tig  = lane & 3;
    const int bh   = blockIdx.y;
    const int q0   = blockIdx.x * 128;

    const int mat = lane >> 3, lr = lane & 7;
    const int b_jo  = mat >> 1;
    const int b_col = (mat & 1) * 8;

    const __nv_bfloat16* Kbh = kh + (size_t)bh * SEQ * HD;
    const __nv_bfloat16* Kbl = kl + (size_t)bh * SEQ * HD;
    const __nv_bfloat16* Vbh = vth + (size_t)bh * HD * SEQ;
    const __nv_bfloat16* Vbl = vtl + (size_t)bh * HD * SEQ;

    auto issue_tile = [&](int kt, int stage) {
        const uint32_t st = sbase + stage * AST;
        #pragma unroll
        for (int i = 0; i < 4; i++) {
            int g = tid + i * 128;          // 0..511
            int r = g >> 3, ch = g & 7;
            uint32_t so = (uint32_t)(r * KPITCH + ch * 8) * 2;
            cp_async16(st + so,         Kbh + (size_t)(kt * 64 + r) * HD + ch * 8);
            cp_async16(st + 9216 + so,  Kbl + (size_t)(kt * 64 + r) * HD + ch * 8);
            cp_async16(st + 18432 + so, Vbh + (size_t)r * SEQ + kt * 64 + ch * 8);
            cp_async16(st + 27648 + so, Vbl + (size_t)r * SEQ + kt * 64 + ch * 8);
        }
        CP_COMMIT();
    };

    issue_tile(0, 0);

    // Q fragments for 2 m-tiles (rows q0 + wid*32 + mt*16 ...)
    uint32_t qfh[2][4][4], qfl[2][4][4];
    #pragma unroll
    for (int mt = 0; mt < 2; mt++) {
        const __nv_bfloat16* Qh = qh + ((size_t)bh * SEQ + q0 + wid * 32 + mt * 16) * HD;
        const __nv_bfloat16* Ql = ql + ((size_t)bh * SEQ + q0 + wid * 32 + mt * 16) * HD;
        #pragma unroll
        for (int cc = 0; cc < 4; cc++) {
            int k0 = cc * 16 + 2 * tig;
            qfh[mt][cc][0] = *(const uint32_t*)(Qh + grp * HD + k0);
            qfh[mt][cc][1] = *(const uint32_t*)(Qh + (grp + 8) * HD + k0);
            qfh[mt][cc][2] = *(const uint32_t*)(Qh + grp * HD + k0 + 8);
            qfh[mt][cc][3] = *(const uint32_t*)(Qh + (grp + 8) * HD + k0 + 8);
            qfl[mt][cc][0] = *(const uint32_t*)(Ql + grp * HD + k0);
            qfl[mt][cc][1] = *(const uint32_t*)(Ql + (grp + 8) * HD + k0);
            qfl[mt][cc][2] = *(const uint32_t*)(Ql + grp * HD + k0 + 8);
            qfl[mt][cc][3] = *(const uint32_t*)(Ql + (grp + 8) * HD + k0 + 8);
        }
    }

    float o[2][8][4];
    #pragma unroll
    for (int mt = 0; mt < 2; mt++)
        #pragma unroll
        for (int j = 0; j < 8; j++)
            #pragma unroll
            for (int p = 0; p < 4; p++) o[mt][j][p] = 0.f;
    float mrow[2][2], lrow[2][2];
    #pragma unroll
    for (int mt = 0; mt < 2; mt++) {
        mrow[mt][0] = -INFINITY; mrow[mt][1] = -INFINITY;
        lrow[mt][0] = 0.f;       lrow[mt][1] = 0.f;
    }

    const int NT = SEQ / 64;
    for (int kt = 0; kt < NT; kt++) {
        if (kt + 1 < NT) {
            issue_tile(kt + 1, (kt + 1) & 1);
            CP_WAIT(1);
        } else {
            CP_WAIT(0);
        }
        __syncthreads();

        const uint32_t st = sbase + (kt & 1) * AST;

        // ---- S = Q K^T (3-pass, each K-frag feeds both m-tiles) ----
        float s[2][8][4];
        #pragma unroll
        for (int mt = 0; mt < 2; mt++)
            #pragma unroll
            for (int j = 0; j < 8; j++)
                #pragma unroll
                for (int p = 0; p < 4; p++) s[mt][j][p] = 0.f;
        #pragma unroll
        for (int cc = 0; cc < 4; cc++) {
            #pragma unroll
            for (int p = 0; p < 4; p++) {
                uint32_t kf_h[4], kf_l[4];
                uint32_t kd = st + (uint32_t)(((p * 2 + b_jo) * 8 + lr) * KPITCH
                                              + cc * 16 + b_col) * 2;
                ldsm4(kf_h, kd);
                ldsm4(kf_l, kd + 9216);
                #pragma unroll
                for (int mt = 0; mt < 2; mt++) {
                    mma16816(s[mt][2 * p],     qfh[mt][cc], &kf_h[0]);
                    mma16816(s[mt][2 * p],     qfh[mt][cc], &kf_l[0]);
                    mma16816(s[mt][2 * p],     qfl[mt][cc], &kf_h[0]);
                    mma16816(s[mt][2 * p + 1], qfh[mt][cc], &kf_h[2]);
                    mma16816(s[mt][2 * p + 1], qfh[mt][cc], &kf_l[2]);
                    mma16816(s[mt][2 * p + 1], qfl[mt][cc], &kf_h[2]);
                }
            }
        }

        // ---- online softmax + P packing, per m-tile ----
        uint32_t pfh[2][4][4], pfl[2][4][4];
        #pragma unroll
        for (int mt = 0; mt < 2; mt++) {
            float mx0 = -INFINITY, mx1 = -INFINITY;
            #pragma unroll
            for (int j = 0; j < 8; j++) {
                mx0 = fmaxf(mx0, fmaxf(s[mt][j][0], s[mt][j][1]));
                mx1 = fmaxf(mx1, fmaxf(s[mt][j][2], s[mt][j][3]));
            }
            mx0 = fmaxf(mx0, __shfl_xor_sync(0xffffffffu, mx0, 1));
            mx0 = fmaxf(mx0, __shfl_xor_sync(0xffffffffu, mx0, 2));
            mx1 = fmaxf(mx1, __shfl_xor_sync(0xffffffffu, mx1, 1));
            mx1 = fmaxf(mx1, __shfl_xor_sync(0xffffffffu, mx1, 2));
            float mn0 = fmaxf(mrow[mt][0], mx0), mn1 = fmaxf(mrow[mt][1], mx1);
            float a0 = __expf(mrow[mt][0] - mn0), a1 = __expf(mrow[mt][1] - mn1);
            mrow[mt][0] = mn0; mrow[mt][1] = mn1;

            float ps0 = 0.f, ps1 = 0.f;
            #pragma unroll
            for (int j = 0; j < 8; j++) {
                float p0 = __expf(s[mt][j][0] - mn0);
                float p1 = __expf(s[mt][j][1] - mn0);
                float p2 = __expf(s[mt][j][2] - mn1);
                float p3 = __expf(s[mt][j][3] - mn1);
                ps0 += p0 + p1;
                ps1 += p2 + p3;
                int cc = j >> 1, half = j & 1;
                __nv_bfloat162 lo2a, lo2b;
                __nv_bfloat162 hi2a = split_pack(p0, p1, &lo2a);
                __nv_bfloat162 hi2b = split_pack(p2, p3, &lo2b);
                pfh[mt][cc][0 + 2 * half] = *(uint32_t*)&hi2a;
                pfh[mt][cc][1 + 2 * half] = *(uint32_t*)&hi2b;
                pfl[mt][cc][0 + 2 * half] = *(uint32_t*)&lo2a;
                pfl[mt][cc][1 + 2 * half] = *(uint32_t*)&lo2b;
            }
            ps0 += __shfl_xor_sync(0xffffffffu, ps0, 1);
            ps0 += __shfl_xor_sync(0xffffffffu, ps0, 2);
            ps1 += __shfl_xor_sync(0xffffffffu, ps1, 1);
            ps1 += __shfl_xor_sync(0xffffffffu, ps1, 2);
            lrow[mt][0] = lrow[mt][0] * a0 + ps0;
            lrow[mt][1] = lrow[mt][1] * a1 + ps1;

            #pragma unroll
            for (int j = 0; j < 8; j++) {
                o[mt][j][0] *= a0; o[mt][j][1] *= a0;
                o[mt][j][2] *= a1; o[mt][j][3] *= a1;
            }
        }

        // ---- O += P V (3-pass, each V-frag feeds both m-tiles) ----
        #pragma unroll
        for (int cc = 0; cc < 4; cc++) {
            #pragma unroll
            for (int p = 0; p < 4; p++) {
                uint32_t vf_h[4], vf_l[4];
                uint32_t vd = st + 18432 +
                    (uint32_t)(((p * 2 + b_jo) * 8 + lr) * KPITCH + cc * 16 + b_col) * 2;
                ldsm4(vf_h, vd);
                ldsm4(vf_l, vd + 9216);
                #pragma unroll
                for (int mt = 0; mt < 2; mt++) {
                    mma16816(o[mt][2 * p],     pfh[mt][cc], &vf_h[0]);
                    mma16816(o[mt][2 * p],     pfh[mt][cc], &vf_l[0]);
                    mma16816(o[mt][2 * p],     pfl[mt][cc], &vf_h[0]);
                    mma16816(o[mt][2 * p + 1], pfh[mt][cc], &vf_h[2]);
                    mma16816(o[mt][2 * p + 1], pfh[mt][cc], &vf_l[2]);
                    mma16816(o[mt][2 * p + 1], pfl[mt][cc], &vf_h[2]);
                }
            }
        }
        __syncthreads();
    }

    // ---- epilogue ----
    const int b = bh >> 4;
    const int h = bh & 15;
    #pragma unroll
    for (int mt = 0; mt < 2; mt++) {
        float inv0 = 1.0f / lrow[mt][0], inv1 = 1.0f / lrow[mt][1];
        int s0 = q0 + wid * 32 + mt * 16 + grp;
        int s1 = s0 + 8;
        #pragma unroll
        for (int j = 0; j < 8; j++) {
            int col = h * HD + j * 8 + 2 * tig;
            __nv_bfloat162 lo2;
            __nv_bfloat162 hi2 = split_pack(o[mt][j][0] * inv0, o[mt][j][1] * inv0, &lo2);
            size_t off0 = ((size_t)b * SEQ + s0) * HIDDEN + col;
            *(__nv_bfloat162*)(Ohi + off0) = hi2;
            *(__nv_bfloat162*)(Olo + off0) = lo2;
            hi2 = split_pack(o[mt][j][2] * inv1, o[mt][j][3] * inv1, &lo2);
            size_t off1 = ((size_t)b * SEQ + s1) * HIDDEN + col;
            *(__nv_bfloat162*)(Ohi + off1) = hi2;
            *(__nv_bfloat162*)(Olo + off1) = lo2;
        }
    }
}

// ---------------------------------------------------------------------------
extern "C" void kernel_launch(void* const* d_in, const int* in_sizes, int n_in,
                              void* d_out, int out_size)
{
    const float* x     = (const float*)d_in[0];
    const float* W_qkv = (const float*)d_in[1];
    const float* b_qkv = (const float*)d_in[2];
    const float* W_out = (const float*)d_in[3];
    const float* b_out = (const float*)d_in[4];
    float* out = (float*)d_out;

    static __nv_bfloat16 *pah = nullptr, *pal, *pwqh, *pwql, *pwoh, *pwol;
    static __nv_bfloat16 *pqh, *pql, *pkh, *pkl, *pvth, *pvtl;
    if (!pah) {
        cudaGetSymbolAddress((void**)&pah, g_a_hi);
        cudaGetSymbolAddress((void**)&pal, g_a_lo);
        cudaGetSymbolAddress((void**)&pwqh, g_wq_hi);
        cudaGetSymbolAddress((void**)&pwql, g_wq_lo);
        cudaGetSymbolAddress((void**)&pwoh, g_wo_hi);
        cudaGetSymbolAddress((void**)&pwol, g_wo_lo);
        cudaGetSymbolAddress((void**)&pqh, g_qh);
        cudaGetSymbolAddress((void**)&pql, g_ql);
        cudaGetSymbolAddress((void**)&pkh, g_kh);
        cudaGetSymbolAddress((void**)&pkl, g_kl);
        cudaGetSymbolAddress((void**)&pvth, g_vth);
        cudaGetSymbolAddress((void**)&pvtl, g_vtl);
        cudaFuncSetAttribute(hmma_gemm, cudaFuncAttributeMaxDynamicSharedMemorySize, GEMM_SMEM);
        cudaFuncSetAttribute(attn_hmma, cudaFuncAttributeMaxDynamicSharedMemorySize, ATTN_SMEM);
    }

    const int n4 = MTOT * HIDDEN / 4;

    split_kernel<<<n4 / 256, 256>>>(x, pah, pal, n4);
    {
        dim3 g(3 * HIDDEN / 32, HIDDEN / 32);
        tsplit_kernel<<<g, dim3(32, 8)>>>(W_qkv, pwqh, pwql, HIDDEN, 3 * HIDDEN);
    }
    {
        dim3 g(HIDDEN / 32, HIDDEN / 32);
        tsplit_kernel<<<g, dim3(32, 8)>>>(W_out, pwoh, pwol, HIDDEN, HIDDEN);
    }

    {
        dim3 g(3 * HIDDEN / 128, MTOT / 128);   // (24, 64)
        hmma_gemm<<<g, 128, GEMM_SMEM>>>(pah, pal, pwqh, pwql, b_qkv, nullptr,
                                         pqh, pql, pkh, pkl, pvth, pvtl,
                                         MTOT, 3 * HIDDEN, HIDDEN, 1);
    }

    {
        dim3 g(SEQ / 128, BATCH * HEADS);       // (16, 64)
        attn_hmma<<<g, 128, ATTN_SMEM>>>(pqh, pql, pkh, pkl, pvth, pvtl, pah, pal);
    }

    {
        dim3 g(HIDDEN / 128, MTOT / 128);       // (8, 64)
        hmma_gemm<<<g, 128, GEMM_SMEM>>>(pah, pal, pwoh, pwol, b_out, out,
                                         nullptr, nullptr, nullptr, nullptr, nullptr, nullptr,
                                         MTOT, HIDDEN, HIDDEN, 0);
    }
}

// round 10
// speedup vs baseline: 1.2703x; 1.2703x over previous
#include <cuda_runtime.h>
#include <cuda_bf16.h>
#include <cuda_fp16.h>
#include <math.h>
#include <stdint.h>

#define HIDDEN 1024
#define HEADS  16
#define HD     64
#define BATCH  4
#define SEQ    2048
#define MTOT   (BATCH * SEQ)   // 8192

// ---------------- scratch (device globals; no allocs allowed) --------------
__device__ __nv_bfloat16 g_a_hi[MTOT * HIDDEN];
__device__ __nv_bfloat16 g_a_lo[MTOT * HIDDEN];
__device__ __nv_bfloat16 g_wq_hi[3 * HIDDEN * HIDDEN];
__device__ __nv_bfloat16 g_wq_lo[3 * HIDDEN * HIDDEN];
__device__ __nv_bfloat16 g_wo_hi[HIDDEN * HIDDEN];
__device__ __nv_bfloat16 g_wo_lo[HIDDEN * HIDDEN];
// attention operands (fp16): Q single (pre-scaled), K hi/lo, V^T hi/lo
__device__ __half g_qf[BATCH * HEADS * SEQ * HD];
__device__ __half g_kh[BATCH * HEADS * SEQ * HD];
__device__ __half g_kl[BATCH * HEADS * SEQ * HD];
__device__ __half g_vth[BATCH * HEADS * HD * SEQ];
__device__ __half g_vtl[BATCH * HEADS * HD * SEQ];

// ---------------- async-copy / ldmatrix helpers -----------------------------
__device__ __forceinline__ void cp_async16(uint32_t saddr, const void* gptr) {
    asm volatile("cp.async.ca.shared.global [%0], [%1], 16;"
                 :: "r"(saddr), "l"(gptr));
}
#define CP_COMMIT()  asm volatile("cp.async.commit_group;" ::: "memory")
#define CP_WAIT(n)   asm volatile("cp.async.wait_group %0;" :: "n"(n) : "memory")

__device__ __forceinline__ void ldsm4(uint32_t* r, uint32_t addr) {
    asm volatile("ldmatrix.sync.aligned.m8n8.x4.shared.b16 {%0,%1,%2,%3}, [%4];"
                 : "=r"(r[0]), "=r"(r[1]), "=r"(r[2]), "=r"(r[3]) : "r"(addr));
}

// ---------------------------------------------------------------------------
__global__ __launch_bounds__(256) void split_kernel(
    const float* __restrict__ src, __nv_bfloat16* __restrict__ hi,
    __nv_bfloat16* __restrict__ lo, int n4)
{
    int i = blockIdx.x * blockDim.x + threadIdx.x;
    if (i >= n4) return;
    float4 v = ((const float4*)src)[i];
    float xs[4] = {v.x, v.y, v.z, v.w};
    __nv_bfloat16 h[4], l[4];
    #pragma unroll
    for (int j = 0; j < 4; j++) {
        h[j] = __float2bfloat16_rn(xs[j]);
        l[j] = __float2bfloat16_rn(xs[j] - __bfloat162float(h[j]));
    }
    ((__nv_bfloat162*)hi)[2 * i]     = __nv_bfloat162(h[0], h[1]);
    ((__nv_bfloat162*)hi)[2 * i + 1] = __nv_bfloat162(h[2], h[3]);
    ((__nv_bfloat162*)lo)[2 * i]     = __nv_bfloat162(l[0], l[1]);
    ((__nv_bfloat162*)lo)[2 * i + 1] = __nv_bfloat162(l[2], l[3]);
}

__global__ void tsplit_kernel(const float* __restrict__ W,
                              __nv_bfloat16* __restrict__ hi,
                              __nv_bfloat16* __restrict__ lo, int K, int N)
{
    __shared__ float t[32][33];
    int n0 = blockIdx.x * 32, k0 = blockIdx.y * 32;
    for (int r = threadIdx.y; r < 32; r += 8)
        t[r][threadIdx.x] = W[(size_t)(k0 + r) * N + n0 + threadIdx.x];
    __syncthreads();
    for (int r = threadIdx.y; r < 32; r += 8) {
        float x = t[threadIdx.x][r];
        __nv_bfloat16 h = __float2bfloat16_rn(x);
        __nv_bfloat16 l = __float2bfloat16_rn(x - __bfloat162float(h));
        size_t o = (size_t)(n0 + r) * K + k0 + threadIdx.x;
        hi[o] = h;
        lo[o] = l;
    }
}

// ---------------------------------------------------------------------------
__device__ __forceinline__ void mma16816(float* c, const uint32_t* a, const uint32_t* b)
{
    asm volatile(
        "mma.sync.aligned.m16n8k16.row.col.f32.bf16.bf16.f32 "
        "{%0,%1,%2,%3}, {%4,%5,%6,%7}, {%8,%9}, {%0,%1,%2,%3};"
        : "+f"(c[0]), "+f"(c[1]), "+f"(c[2]), "+f"(c[3])
        : "r"(a[0]), "r"(a[1]), "r"(a[2]), "r"(a[3]), "r"(b[0]), "r"(b[1]));
}

__device__ __forceinline__ void mma16816h(float* c, const uint32_t* a, const uint32_t* b)
{
    asm volatile(
        "mma.sync.aligned.m16n8k16.row.col.f32.f16.f16.f32 "
        "{%0,%1,%2,%3}, {%4,%5,%6,%7}, {%8,%9}, {%0,%1,%2,%3};"
        : "+f"(c[0]), "+f"(c[1]), "+f"(c[2]), "+f"(c[3])
        : "r"(a[0]), "r"(a[1]), "r"(a[2]), "r"(a[3]), "r"(b[0]), "r"(b[1]));
}

__device__ __forceinline__ __nv_bfloat162 split_pack(float x, float y,
                                                     __nv_bfloat162* lo)
{
    __nv_bfloat16 hx = __float2bfloat16_rn(x);
    __nv_bfloat16 hy = __float2bfloat16_rn(y);
    *lo = __nv_bfloat162(__float2bfloat16_rn(x - __bfloat162float(hx)),
                         __float2bfloat16_rn(y - __bfloat162float(hy)));
    return __nv_bfloat162(hx, hy);
}

__device__ __forceinline__ __half2 hsplit2(float x, float y, __half2* lo)
{
    __half hx = __float2half_rn(x);
    __half hy = __float2half_rn(y);
    *lo = __halves2half2(__float2half_rn(x - __half2float(hx)),
                         __float2half_rn(y - __half2float(hy)));
    return __halves2half2(hx, hy);
}

// ---------------------------------------------------------------------------
// HMMA GEMM: CTA 128x128, 4 warps (2x2), warp tile 64x64, bf16 3-pass.
// cp.async 2-stage + ldmatrix. 2 CTAs/SM.
// mode 0: C + bias (fp32). mode 1: QKV epilogue -> Q fp16 (scaled), K fp16
// hi/lo [B,H,S,64], V^T fp16 hi/lo [B,H,64,S].
// ---------------------------------------------------------------------------
#define SPAD 40
#define GST  40960
#define GEMM_SMEM (2 * GST)

__global__ __launch_bounds__(128, 2) void hmma_gemm(
    const __nv_bfloat16* __restrict__ Ahi, const __nv_bfloat16* __restrict__ Alo,
    const __nv_bfloat16* __restrict__ Bhi, const __nv_bfloat16* __restrict__ Blo,
    const float* __restrict__ bias, float* __restrict__ C,
    __half* __restrict__ qf,
    __half* __restrict__ kh, __half* __restrict__ kl,
    __half* __restrict__ vth, __half* __restrict__ vtl,
    int M, int N, int K, int mode)
{
    extern __shared__ char smem[];
    const uint32_t sbase = (uint32_t)__cvta_generic_to_shared(smem);

    const int tid  = threadIdx.x;
    const int wid  = tid >> 5;
    const int lane = tid & 31;
    const int grp  = lane >> 2;
    const int tig  = lane & 3;
    const int wm   = wid & 1;
    const int wn   = wid >> 1;
    const int bm   = blockIdx.y * 128;
    const int bn   = blockIdx.x * 128;
    const int NT   = K / 32;

    const int mat = lane >> 3, lr = lane & 7;
    const int a_row = (mat & 1) * 8 + lr;
    const int a_col = (mat >> 1) * 8;
    const int b_jo  = mat >> 1;
    const int b_col = (mat & 1) * 8;

    float c[4][8][4];
    #pragma unroll
    for (int i = 0; i < 4; i++)
        #pragma unroll
        for (int j = 0; j < 8; j++)
            #pragma unroll
            for (int p = 0; p < 4; p++) c[i][j][p] = 0.f;

    auto issue_tile = [&](int kt, int stage) {
        const int k0 = kt * 32;
        const uint32_t st = sbase + stage * GST;
        #pragma unroll
        for (int u = 0; u < 4; u++) {
            int g = tid + u * 128;
            int r = g >> 2, ch = g & 3;
            uint32_t so = (uint32_t)(r * SPAD + ch * 8) * 2;
            size_t ga = (size_t)(bm + r) * K + k0 + ch * 8;
            size_t gb = (size_t)(bn + r) * K + k0 + ch * 8;
            cp_async16(st + so,         Ahi + ga);
            cp_async16(st + 10240 + so, Alo + ga);
            cp_async16(st + 20480 + so, Bhi + gb);
            cp_async16(st + 30720 + so, Blo + gb);
        }
        CP_COMMIT();
    };

    issue_tile(0, 0);

    for (int kt = 0; kt < NT; kt++) {
        if (kt + 1 < NT) {
            issue_tile(kt + 1, (kt + 1) & 1);
            CP_WAIT(1);
        } else {
            CP_WAIT(0);
        }
        __syncthreads();

        const uint32_t st = sbase + (kt & 1) * GST;

        #pragma unroll
        for (int ks = 0; ks < 2; ks++) {
            const int kk = ks * 16;
            uint32_t ah[4][4], al[4][4], bh[4][4], bl[4][4];
            #pragma unroll
            for (int i = 0; i < 4; i++) {
                uint32_t ad = st + (uint32_t)((wm * 64 + i * 16 + a_row) * SPAD + kk + a_col) * 2;
                ldsm4(ah[i], ad);
                ldsm4(al[i], ad + 10240);
            }
            #pragma unroll
            for (int p = 0; p < 4; p++) {
                uint32_t bd = st + 20480 +
                    (uint32_t)((wn * 64 + (p * 2 + b_jo) * 8 + lr) * SPAD + kk + b_col) * 2;
                ldsm4(bh[p], bd);
                ldsm4(bl[p], bd + 10240);
            }
            #pragma unroll
            for (int i = 0; i < 4; i++)
                #pragma unroll
                for (int j = 0; j < 8; j++)
                    mma16816(c[i][j], ah[i], &bh[j >> 1][(j & 1) * 2]);
            #pragma unroll
            for (int i = 0; i < 4; i++)
                #pragma unroll
                for (int j = 0; j < 8; j++)
                    mma16816(c[i][j], ah[i], &bl[j >> 1][(j & 1) * 2]);
            #pragma unroll
            for (int i = 0; i < 4; i++)
                #pragma unroll
                for (int j = 0; j < 8; j++)
                    mma16816(c[i][j], al[i], &bh[j >> 1][(j & 1) * 2]);
        }
        __syncthreads();
    }

    #pragma unroll
    for (int i = 0; i < 4; i++) {
        #pragma unroll
        for (int j = 0; j < 8; j++) {
            int n0 = bn + wn * 64 + j * 8 + tig * 2;
            float2 bv = *(const float2*)(bias + n0);
            #pragma unroll
            for (int half = 0; half < 2; half++) {
                int m = bm + wm * 64 + i * 16 + grp + half * 8;
                float rx = c[i][j][half * 2 + 0] + bv.x;
                float ry = c[i][j][half * 2 + 1] + bv.y;
                if (mode == 0) {
                    *(float2*)(C + (size_t)m * N + n0) = make_float2(rx, ry);
                } else {
                    int sel = n0 >> 10, rem = n0 & 1023;
                    int h = rem >> 6, hd0 = rem & 63;
                    int b = m >> 11, s = m & 2047;
                    size_t bh_ = (size_t)b * HEADS + h;
                    if (sel == 0) {
                        size_t off = (bh_ * SEQ + s) * HD + hd0;
                        *(__half2*)(qf + off) =
                            __floats2half2_rn(rx * 0.125f, ry * 0.125f);
                    } else if (sel == 1) {
                        __half2 lo2;
                        __half2 hi2 = hsplit2(rx, ry, &lo2);
                        size_t off = (bh_ * SEQ + s) * HD + hd0;
                        *(__half2*)(kh + off) = hi2;
                        *(__half2*)(kl + off) = lo2;
                    } else {
                        __half2 lo2;
                        __half2 hi2 = hsplit2(rx, ry, &lo2);
                        size_t o0 = (bh_ * HD + hd0) * SEQ + s;
                        size_t o1 = (bh_ * HD + hd0 + 1) * SEQ + s;
                        vth[o0] = __low2half(hi2); vth[o1] = __high2half(hi2);
                        vtl[o0] = __low2half(lo2); vtl[o1] = __high2half(lo2);
                    }
                }
            }
        }
    }
}

// ---------------------------------------------------------------------------
// fp16 2-pass HMMA flash attention (R8 shape): 128 q-rows/CTA, 8 warps x
// 16 q-rows, 64-key tiles, cp.async 2-stage + ldmatrix, 2 CTAs/SM.
// S = Q*Kh + Q*Kl ; O += P*Vh + P*Vl  (Q and P single fp16).
// ---------------------------------------------------------------------------
#define KPITCH 72
#define AST    36864
#define ATTN_SMEM (2 * AST)

__global__ __launch_bounds__(256, 2) void attn_hmma(
    const __half* __restrict__ qf,
    const __half* __restrict__ kh, const __half* __restrict__ kl,
    const __half* __restrict__ vth, const __half* __restrict__ vtl,
    __nv_bfloat16* __restrict__ Ohi, __nv_bfloat16* __restrict__ Olo)
{
    extern __shared__ char smem[];
    const uint32_t sbase = (uint32_t)__cvta_generic_to_shared(smem);

    const int tid  = threadIdx.x;
    const int wid  = tid >> 5;
    const int lane = tid & 31;
    const int grp  = lane >> 2;
    const int tig  = lane & 3;
    const int bh   = blockIdx.y;
    const int q0   = blockIdx.x * 128;

    const int mat = lane >> 3, lr = lane & 7;
    const int b_jo  = mat >> 1;
    const int b_col = (mat & 1) * 8;

    const __half* Kbh = kh + (size_t)bh * SEQ * HD;
    const __half* Kbl = kl + (size_t)bh * SEQ * HD;
    const __half* Vbh = vth + (size_t)bh * HD * SEQ;
    const __half* Vbl = vtl + (size_t)bh * HD * SEQ;

    auto issue_tile = [&](int kt, int stage) {
        const uint32_t st = sbase + stage * AST;
        #pragma unroll
        for (int i = 0; i < 2; i++) {
            int g = tid + i * 256;
            int r = g >> 3, ch = g & 7;
            uint32_t so = (uint32_t)(r * KPITCH + ch * 8) * 2;
            cp_async16(st + so,         Kbh + (size_t)(kt * 64 + r) * HD + ch * 8);
            cp_async16(st + 9216 + so,  Kbl + (size_t)(kt * 64 + r) * HD + ch * 8);
            cp_async16(st + 18432 + so, Vbh + (size_t)r * SEQ + kt * 64 + ch * 8);
            cp_async16(st + 27648 + so, Vbl + (size_t)r * SEQ + kt * 64 + ch * 8);
        }
        CP_COMMIT();
    };

    issue_tile(0, 0);

    // Q fragments (single fp16, loaded once)
    uint32_t qfr[4][4];
    {
        const __half* Qp = qf + ((size_t)bh * SEQ + q0 + wid * 16) * HD;
        #pragma unroll
        for (int cc = 0; cc < 4; cc++) {
            int k0 = cc * 16 + 2 * tig;
            qfr[cc][0] = *(const uint32_t*)(Qp + grp * HD + k0);
            qfr[cc][1] = *(const uint32_t*)(Qp + (grp + 8) * HD + k0);
            qfr[cc][2] = *(const uint32_t*)(Qp + grp * HD + k0 + 8);
            qfr[cc][3] = *(const uint32_t*)(Qp + (grp + 8) * HD + k0 + 8);
        }
    }

    float o[8][4];
    #pragma unroll
    for (int j = 0; j < 8; j++)
        #pragma unroll
        for (int p = 0; p < 4; p++) o[j][p] = 0.f;
    float m0 = -INFINITY, m1 = -INFINITY, l0 = 0.f, l1 = 0.f;

    const int NT = SEQ / 64;
    for (int kt = 0; kt < NT; kt++) {
        if (kt + 1 < NT) {
            issue_tile(kt + 1, (kt + 1) & 1);
            CP_WAIT(1);
        } else {
            CP_WAIT(0);
        }
        __syncthreads();

        const uint32_t st = sbase + (kt & 1) * AST;

        // ---- S = Q*Kh + Q*Kl (2-pass) ----
        float s[8][4];
        #pragma unroll
        for (int j = 0; j < 8; j++)
            #pragma unroll
            for (int p = 0; p < 4; p++) s[j][p] = 0.f;
        #pragma unroll
        for (int cc = 0; cc < 4; cc++) {
            #pragma unroll
            for (int p = 0; p < 4; p++) {
                uint32_t kf_h[4], kf_l[4];
                uint32_t kd = st + (uint32_t)(((p * 2 + b_jo) * 8 + lr) * KPITCH
                                              + cc * 16 + b_col) * 2;
                ldsm4(kf_h, kd);
                ldsm4(kf_l, kd + 9216);
                mma16816h(s[2 * p],     qfr[cc], &kf_h[0]);
                mma16816h(s[2 * p],     qfr[cc], &kf_l[0]);
                mma16816h(s[2 * p + 1], qfr[cc], &kf_h[2]);
                mma16816h(s[2 * p + 1], qfr[cc], &kf_l[2]);
            }
        }

        // ---- online softmax ----
        float mx0 = -INFINITY, mx1 = -INFINITY;
        #pragma unroll
        for (int j = 0; j < 8; j++) {
            mx0 = fmaxf(mx0, fmaxf(s[j][0], s[j][1]));
            mx1 = fmaxf(mx1, fmaxf(s[j][2], s[j][3]));
        }
        mx0 = fmaxf(mx0, __shfl_xor_sync(0xffffffffu, mx0, 1));
        mx0 = fmaxf(mx0, __shfl_xor_sync(0xffffffffu, mx0, 2));
        mx1 = fmaxf(mx1, __shfl_xor_sync(0xffffffffu, mx1, 1));
        mx1 = fmaxf(mx1, __shfl_xor_sync(0xffffffffu, mx1, 2));
        float mn0 = fmaxf(m0, mx0), mn1 = fmaxf(m1, mx1);
        float a0 = __expf(m0 - mn0), a1 = __expf(m1 - mn1);
        m0 = mn0; m1 = mn1;

        uint32_t pfr[4][4];
        float ps0 = 0.f, ps1 = 0.f;
        #pragma unroll
        for (int j = 0; j < 8; j++) {
            float p0 = __expf(s[j][0] - m0);
            float p1 = __expf(s[j][1] - m0);
            float p2 = __expf(s[j][2] - m1);
            float p3 = __expf(s[j][3] - m1);
            ps0 += p0 + p1;
            ps1 += p2 + p3;
            int cc = j >> 1, half = j & 1;
            __half2 pa = __floats2half2_rn(p0, p1);
            __half2 pb = __floats2half2_rn(p2, p3);
            pfr[cc][0 + 2 * half] = *(uint32_t*)&pa;
            pfr[cc][1 + 2 * half] = *(uint32_t*)&pb;
        }
        ps0 += __shfl_xor_sync(0xffffffffu, ps0, 1);
        ps0 += __shfl_xor_sync(0xffffffffu, ps0, 2);
        ps1 += __shfl_xor_sync(0xffffffffu, ps1, 1);
        ps1 += __shfl_xor_sync(0xffffffffu, ps1, 2);
        l0 = l0 * a0 + ps0;
        l1 = l1 * a1 + ps1;

        #pragma unroll
        for (int j = 0; j < 8; j++) {
            o[j][0] *= a0; o[j][1] *= a0;
            o[j][2] *= a1; o[j][3] *= a1;
        }

        // ---- O += P*Vh + P*Vl (2-pass) ----
        #pragma unroll
        for (int cc = 0; cc < 4; cc++) {
            #pragma unroll
            for (int p = 0; p < 4; p++) {
                uint32_t vf_h[4], vf_l[4];
                uint32_t vd = st + 18432 +
                    (uint32_t)(((p * 2 + b_jo) * 8 + lr) * KPITCH + cc * 16 + b_col) * 2;
                ldsm4(vf_h, vd);
                ldsm4(vf_l, vd + 9216);
                mma16816h(o[2 * p],     pfr[cc], &vf_h[0]);
                mma16816h(o[2 * p],     pfr[cc], &vf_l[0]);
                mma16816h(o[2 * p + 1], pfr[cc], &vf_h[2]);
                mma16816h(o[2 * p + 1], pfr[cc], &vf_l[2]);
            }
        }
        __syncthreads();
    }

    // ---- epilogue: O / l, bf16 hi/lo split into [B,S,H*64] ----
    const int b = bh >> 4;
    const int h = bh & 15;
    float inv0 = 1.0f / l0, inv1 = 1.0f / l1;
    int s0 = q0 + wid * 16 + grp;
    int s1 = s0 + 8;
    #pragma unroll
    for (int j = 0; j < 8; j++) {
        int col = h * HD + j * 8 + 2 * tig;
        __nv_bfloat162 lo2;
        __nv_bfloat162 hi2 = split_pack(o[j][0] * inv0, o[j][1] * inv0, &lo2);
        size_t off0 = ((size_t)b * SEQ + s0) * HIDDEN + col;
        *(__nv_bfloat162*)(Ohi + off0) = hi2;
        *(__nv_bfloat162*)(Olo + off0) = lo2;
        hi2 = split_pack(o[j][2] * inv1, o[j][3] * inv1, &lo2);
        size_t off1 = ((size_t)b * SEQ + s1) * HIDDEN + col;
        *(__nv_bfloat162*)(Ohi + off1) = hi2;
        *(__nv_bfloat162*)(Olo + off1) = lo2;
    }
}

// ---------------------------------------------------------------------------
extern "C" void kernel_launch(void* const* d_in, const int* in_sizes, int n_in,
                              void* d_out, int out_size)
{
    const float* x     = (const float*)d_in[0];
    const float* W_qkv = (const float*)d_in[1];
    const float* b_qkv = (const float*)d_in[2];
    const float* W_out = (const float*)d_in[3];
    const float* b_out = (const float*)d_in[4];
    float* out = (float*)d_out;

    static __nv_bfloat16 *pah = nullptr, *pal, *pwqh, *pwql, *pwoh, *pwol;
    static __half *pqf, *pkh, *pkl, *pvth, *pvtl;
    if (!pah) {
        cudaGetSymbolAddress((void**)&pah, g_a_hi);
        cudaGetSymbolAddress((void**)&pal, g_a_lo);
        cudaGetSymbolAddress((void**)&pwqh, g_wq_hi);
        cudaGetSymbolAddress((void**)&pwql, g_wq_lo);
        cudaGetSymbolAddress((void**)&pwoh, g_wo_hi);
        cudaGetSymbolAddress((void**)&pwol, g_wo_lo);
        cudaGetSymbolAddress((void**)&pqf, g_qf);
        cudaGetSymbolAddress((void**)&pkh, g_kh);
        cudaGetSymbolAddress((void**)&pkl, g_kl);
        cudaGetSymbolAddress((void**)&pvth, g_vth);
        cudaGetSymbolAddress((void**)&pvtl, g_vtl);
        cudaFuncSetAttribute(hmma_gemm, cudaFuncAttributeMaxDynamicSharedMemorySize, GEMM_SMEM);
        cudaFuncSetAttribute(attn_hmma, cudaFuncAttributeMaxDynamicSharedMemorySize, ATTN_SMEM);
    }

    const int n4 = MTOT * HIDDEN / 4;

    split_kernel<<<n4 / 256, 256>>>(x, pah, pal, n4);
    {
        dim3 g(3 * HIDDEN / 32, HIDDEN / 32);
        tsplit_kernel<<<g, dim3(32, 8)>>>(W_qkv, pwqh, pwql, HIDDEN, 3 * HIDDEN);
    }
    {
        dim3 g(HIDDEN / 32, HIDDEN / 32);
        tsplit_kernel<<<g, dim3(32, 8)>>>(W_out, pwoh, pwol, HIDDEN, HIDDEN);
    }

    {
        dim3 g(3 * HIDDEN / 128, MTOT / 128);   // (24, 64)
        hmma_gemm<<<g, 128, GEMM_SMEM>>>(pah, pal, pwqh, pwql, b_qkv, nullptr,
                                         pqf, pkh, pkl, pvth, pvtl,
                                         MTOT, 3 * HIDDEN, HIDDEN, 1);
    }

    {
        dim3 g(SEQ / 128, BATCH * HEADS);       // (16, 64)
        attn_hmma<<<g, 256, ATTN_SMEM>>>(pqf, pkh, pkl, pvth, pvtl, pah, pal);
    }

    {
        dim3 g(HIDDEN / 128, MTOT / 128);       // (8, 64)
        hmma_gemm<<<g, 128, GEMM_SMEM>>>(pah, pal, pwoh, pwol, b_out, out,
                                         nullptr, nullptr, nullptr, nullptr, nullptr,
                                         MTOT, HIDDEN, HIDDEN, 0);
    }
}

// round 11
// speedup vs baseline: 1.5125x; 1.1907x over previous
#include <cuda_runtime.h>
#include <cuda_bf16.h>
#include <cuda_fp16.h>
#include <math.h>
#include <stdint.h>

#define HIDDEN 1024
#define HEADS  16
#define HD     64
#define BATCH  4
#define SEQ    2048
#define MTOT   (BATCH * SEQ)   // 8192

// ---------------- scratch (device globals; no allocs allowed) --------------
__device__ __half g_xf[MTOT * HIDDEN];                 // activations fp16 (x, then attn out)
__device__ __half g_wq_h[3 * HIDDEN * HIDDEN];         // W_qkv^T hi  [3072,1024]
__device__ __half g_wq_l[3 * HIDDEN * HIDDEN];         // W_qkv^T lo
__device__ __half g_wo_h[HIDDEN * HIDDEN];             // W_out^T hi
__device__ __half g_wo_l[HIDDEN * HIDDEN];             // W_out^T lo
// attention operands (fp16): Q single (pre-scaled), K hi/lo, V^T hi/lo
__device__ __half g_qf[BATCH * HEADS * SEQ * HD];
__device__ __half g_kh[BATCH * HEADS * SEQ * HD];
__device__ __half g_kl[BATCH * HEADS * SEQ * HD];
__device__ __half g_vth[BATCH * HEADS * HD * SEQ];
__device__ __half g_vtl[BATCH * HEADS * HD * SEQ];

// ---------------- async-copy / ldmatrix helpers -----------------------------
__device__ __forceinline__ void cp_async16(uint32_t saddr, const void* gptr) {
    asm volatile("cp.async.ca.shared.global [%0], [%1], 16;"
                 :: "r"(saddr), "l"(gptr));
}
#define CP_COMMIT()  asm volatile("cp.async.commit_group;" ::: "memory")
#define CP_WAIT(n)   asm volatile("cp.async.wait_group %0;" :: "n"(n) : "memory")

__device__ __forceinline__ void ldsm4(uint32_t* r, uint32_t addr) {
    asm volatile("ldmatrix.sync.aligned.m8n8.x4.shared.b16 {%0,%1,%2,%3}, [%4];"
                 : "=r"(r[0]), "=r"(r[1]), "=r"(r[2]), "=r"(r[3]) : "r"(addr));
}

// ---------------------------------------------------------------------------
// cast x -> fp16 (one float4 per thread)
// ---------------------------------------------------------------------------
__global__ __launch_bounds__(256) void cast_kernel(
    const float* __restrict__ src, __half* __restrict__ dst, int n4)
{
    int i = blockIdx.x * blockDim.x + threadIdx.x;
    if (i >= n4) return;
    float4 v = ((const float4*)src)[i];
    ((__half2*)dst)[2 * i]     = __floats2half2_rn(v.x, v.y);
    ((__half2*)dst)[2 * i + 1] = __floats2half2_rn(v.z, v.w);
}

// ---------------------------------------------------------------------------
// transpose + split: W[K,N] fp32 -> Wt hi/lo fp16 [N,K]
// ---------------------------------------------------------------------------
__global__ void tsplit_kernel(const float* __restrict__ W,
                              __half* __restrict__ hi,
                              __half* __restrict__ lo, int K, int N)
{
    __shared__ float t[32][33];
    int n0 = blockIdx.x * 32, k0 = blockIdx.y * 32;
    for (int r = threadIdx.y; r < 32; r += 8)
        t[r][threadIdx.x] = W[(size_t)(k0 + r) * N + n0 + threadIdx.x];
    __syncthreads();
    for (int r = threadIdx.y; r < 32; r += 8) {
        float x = t[threadIdx.x][r];
        __half h = __float2half_rn(x);
        __half l = __float2half_rn(x - __half2float(h));
        size_t o = (size_t)(n0 + r) * K + k0 + threadIdx.x;
        hi[o] = h;
        lo[o] = l;
    }
}

// ---------------------------------------------------------------------------
__device__ __forceinline__ void mma16816h(float* c, const uint32_t* a, const uint32_t* b)
{
    asm volatile(
        "mma.sync.aligned.m16n8k16.row.col.f32.f16.f16.f32 "
        "{%0,%1,%2,%3}, {%4,%5,%6,%7}, {%8,%9}, {%0,%1,%2,%3};"
        : "+f"(c[0]), "+f"(c[1]), "+f"(c[2]), "+f"(c[3])
        : "r"(a[0]), "r"(a[1]), "r"(a[2]), "r"(a[3]), "r"(b[0]), "r"(b[1]));
}

__device__ __forceinline__ __half2 hsplit2(float x, float y, __half2* lo)
{
    __half hx = __float2half_rn(x);
    __half hy = __float2half_rn(y);
    *lo = __halves2half2(__float2half_rn(x - __half2float(hx)),
                         __float2half_rn(y - __half2float(hy)));
    return __halves2half2(hx, hy);
}

// ---------------------------------------------------------------------------
// HMMA GEMM (fp16 2-pass): C[M,N] = A @ (Wh + Wl)^T + bias
// A single fp16 [M,K]; W hi/lo fp16 [N,K]. CTA 128x128, 4 warps (2x2),
// warp tile 64x64. cp.async 2-stage + ldmatrix. 2 CTAs/SM.
// mode 0: C + bias (fp32). mode 1: QKV epilogue.
// smem/stage: A=0 (10240B), Bh=10240, Bl=20480; stride 30720.
// ---------------------------------------------------------------------------
#define SPAD 40
#define GST  30720
#define GEMM_SMEM (2 * GST)

__global__ __launch_bounds__(128, 2) void hmma_gemm(
    const __half* __restrict__ A,
    const __half* __restrict__ Bh, const __half* __restrict__ Bl,
    const float* __restrict__ bias, float* __restrict__ C,
    __half* __restrict__ qf,
    __half* __restrict__ kh, __half* __restrict__ kl,
    __half* __restrict__ vth, __half* __restrict__ vtl,
    int M, int N, int K, int mode)
{
    extern __shared__ char smem[];
    const uint32_t sbase = (uint32_t)__cvta_generic_to_shared(smem);

    const int tid  = threadIdx.x;
    const int wid  = tid >> 5;
    const int lane = tid & 31;
    const int grp  = lane >> 2;
    const int tig  = lane & 3;
    const int wm   = wid & 1;
    const int wn   = wid >> 1;
    const int bm   = blockIdx.y * 128;
    const int bn   = blockIdx.x * 128;
    const int NT   = K / 32;

    const int mat = lane >> 3, lr = lane & 7;
    const int a_row = (mat & 1) * 8 + lr;
    const int a_col = (mat >> 1) * 8;
    const int b_jo  = mat >> 1;
    const int b_col = (mat & 1) * 8;

    float c[4][8][4];
    #pragma unroll
    for (int i = 0; i < 4; i++)
        #pragma unroll
        for (int j = 0; j < 8; j++)
            #pragma unroll
            for (int p = 0; p < 4; p++) c[i][j][p] = 0.f;

    auto issue_tile = [&](int kt, int stage) {
        const int k0 = kt * 32;
        const uint32_t st = sbase + stage * GST;
        #pragma unroll
        for (int u = 0; u < 4; u++) {
            int g = tid + u * 128;          // 0..511
            int r = g >> 2, ch = g & 3;
            uint32_t so = (uint32_t)(r * SPAD + ch * 8) * 2;
            size_t ga = (size_t)(bm + r) * K + k0 + ch * 8;
            size_t gb = (size_t)(bn + r) * K + k0 + ch * 8;
            cp_async16(st + so,         A + ga);
            cp_async16(st + 10240 + so, Bh + gb);
            cp_async16(st + 20480 + so, Bl + gb);
        }
        CP_COMMIT();
    };

    issue_tile(0, 0);

    for (int kt = 0; kt < NT; kt++) {
        if (kt + 1 < NT) {
            issue_tile(kt + 1, (kt + 1) & 1);
            CP_WAIT(1);
        } else {
            CP_WAIT(0);
        }
        __syncthreads();

        const uint32_t st = sbase + (kt & 1) * GST;

        #pragma unroll
        for (int ks = 0; ks < 2; ks++) {
            const int kk = ks * 16;
            uint32_t af[4][4], bh2[4][4], bl2[4][4];
            #pragma unroll
            for (int i = 0; i < 4; i++) {
                uint32_t ad = st + (uint32_t)((wm * 64 + i * 16 + a_row) * SPAD + kk + a_col) * 2;
                ldsm4(af[i], ad);
            }
            #pragma unroll
            for (int p = 0; p < 4; p++) {
                uint32_t bd = st + 10240 +
                    (uint32_t)((wn * 64 + (p * 2 + b_jo) * 8 + lr) * SPAD + kk + b_col) * 2;
                ldsm4(bh2[p], bd);
                ldsm4(bl2[p], bd + 10240);
            }
            // pass 1: A * Wh
            #pragma unroll
            for (int i = 0; i < 4; i++)
                #pragma unroll
                for (int j = 0; j < 8; j++)
                    mma16816h(c[i][j], af[i], &bh2[j >> 1][(j & 1) * 2]);
            // pass 2: A * Wl
            #pragma unroll
            for (int i = 0; i < 4; i++)
                #pragma unroll
                for (int j = 0; j < 8; j++)
                    mma16816h(c[i][j], af[i], &bl2[j >> 1][(j & 1) * 2]);
        }
        __syncthreads();
    }

    #pragma unroll
    for (int i = 0; i < 4; i++) {
        #pragma unroll
        for (int j = 0; j < 8; j++) {
            int n0 = bn + wn * 64 + j * 8 + tig * 2;
            float2 bv = *(const float2*)(bias + n0);
            #pragma unroll
            for (int half = 0; half < 2; half++) {
                int m = bm + wm * 64 + i * 16 + grp + half * 8;
                float rx = c[i][j][half * 2 + 0] + bv.x;
                float ry = c[i][j][half * 2 + 1] + bv.y;
                if (mode == 0) {
                    *(float2*)(C + (size_t)m * N + n0) = make_float2(rx, ry);
                } else {
                    int sel = n0 >> 10, rem = n0 & 1023;
                    int h = rem >> 6, hd0 = rem & 63;
                    int b = m >> 11, s = m & 2047;
                    size_t bh_ = (size_t)b * HEADS + h;
                    if (sel == 0) {
                        size_t off = (bh_ * SEQ + s) * HD + hd0;
                        *(__half2*)(qf + off) =
                            __floats2half2_rn(rx * 0.125f, ry * 0.125f);
                    } else if (sel == 1) {
                        __half2 lo2;
                        __half2 hi2 = hsplit2(rx, ry, &lo2);
                        size_t off = (bh_ * SEQ + s) * HD + hd0;
                        *(__half2*)(kh + off) = hi2;
                        *(__half2*)(kl + off) = lo2;
                    } else {
                        __half2 lo2;
                        __half2 hi2 = hsplit2(rx, ry, &lo2);
                        size_t o0 = (bh_ * HD + hd0) * SEQ + s;
                        size_t o1 = (bh_ * HD + hd0 + 1) * SEQ + s;
                        vth[o0] = __low2half(hi2); vth[o1] = __high2half(hi2);
                        vtl[o0] = __low2half(lo2); vtl[o1] = __high2half(lo2);
                    }
                }
            }
        }
    }
}

// ---------------------------------------------------------------------------
// fp16 2-pass HMMA flash attention: 128 q-rows/CTA, 8 warps x 16 q-rows,
// 64-key tiles, cp.async 2-stage + ldmatrix, 2 CTAs/SM.
// S = Q*Kh + Q*Kl ; O += P*Vh + P*Vl. Output: single fp16 [B,S,H*64].
// ---------------------------------------------------------------------------
#define KPITCH 72
#define AST    36864
#define ATTN_SMEM (2 * AST)

__global__ __launch_bounds__(256, 2) void attn_hmma(
    const __half* __restrict__ qf,
    const __half* __restrict__ kh, const __half* __restrict__ kl,
    const __half* __restrict__ vth, const __half* __restrict__ vtl,
    __half* __restrict__ O)
{
    extern __shared__ char smem[];
    const uint32_t sbase = (uint32_t)__cvta_generic_to_shared(smem);

    const int tid  = threadIdx.x;
    const int wid  = tid >> 5;
    const int lane = tid & 31;
    const int grp  = lane >> 2;
    const int tig  = lane & 3;
    const int bh   = blockIdx.y;
    const int q0   = blockIdx.x * 128;

    const int mat = lane >> 3, lr = lane & 7;
    const int b_jo  = mat >> 1;
    const int b_col = (mat & 1) * 8;

    const __half* Kbh = kh + (size_t)bh * SEQ * HD;
    const __half* Kbl = kl + (size_t)bh * SEQ * HD;
    const __half* Vbh = vth + (size_t)bh * HD * SEQ;
    const __half* Vbl = vtl + (size_t)bh * HD * SEQ;

    auto issue_tile = [&](int kt, int stage) {
        const uint32_t st = sbase + stage * AST;
        #pragma unroll
        for (int i = 0; i < 2; i++) {
            int g = tid + i * 256;
            int r = g >> 3, ch = g & 7;
            uint32_t so = (uint32_t)(r * KPITCH + ch * 8) * 2;
            cp_async16(st + so,         Kbh + (size_t)(kt * 64 + r) * HD + ch * 8);
            cp_async16(st + 9216 + so,  Kbl + (size_t)(kt * 64 + r) * HD + ch * 8);
            cp_async16(st + 18432 + so, Vbh + (size_t)r * SEQ + kt * 64 + ch * 8);
            cp_async16(st + 27648 + so, Vbl + (size_t)r * SEQ + kt * 64 + ch * 8);
        }
        CP_COMMIT();
    };

    issue_tile(0, 0);

    uint32_t qfr[4][4];
    {
        const __half* Qp = qf + ((size_t)bh * SEQ + q0 + wid * 16) * HD;
        #pragma unroll
        for (int cc = 0; cc < 4; cc++) {
            int k0 = cc * 16 + 2 * tig;
            qfr[cc][0] = *(const uint32_t*)(Qp + grp * HD + k0);
            qfr[cc][1] = *(const uint32_t*)(Qp + (grp + 8) * HD + k0);
            qfr[cc][2] = *(const uint32_t*)(Qp + grp * HD + k0 + 8);
            qfr[cc][3] = *(const uint32_t*)(Qp + (grp + 8) * HD + k0 + 8);
        }
    }

    float o[8][4];
    #pragma unroll
    for (int j = 0; j < 8; j++)
        #pragma unroll
        for (int p = 0; p < 4; p++) o[j][p] = 0.f;
    float m0 = -INFINITY, m1 = -INFINITY, l0 = 0.f, l1 = 0.f;

    const int NT = SEQ / 64;
    for (int kt = 0; kt < NT; kt++) {
        if (kt + 1 < NT) {
            issue_tile(kt + 1, (kt + 1) & 1);
            CP_WAIT(1);
        } else {
            CP_WAIT(0);
        }
        __syncthreads();

        const uint32_t st = sbase + (kt & 1) * AST;

        // ---- S = Q*Kh + Q*Kl (2-pass) ----
        float s[8][4];
        #pragma unroll
        for (int j = 0; j < 8; j++)
            #pragma unroll
            for (int p = 0; p < 4; p++) s[j][p] = 0.f;
        #pragma unroll
        for (int cc = 0; cc < 4; cc++) {
            #pragma unroll
            for (int p = 0; p < 4; p++) {
                uint32_t kf_h[4], kf_l[4];
                uint32_t kd = st + (uint32_t)(((p * 2 + b_jo) * 8 + lr) * KPITCH
                                              + cc * 16 + b_col) * 2;
                ldsm4(kf_h, kd);
                ldsm4(kf_l, kd + 9216);
                mma16816h(s[2 * p],     qfr[cc], &kf_h[0]);
                mma16816h(s[2 * p],     qfr[cc], &kf_l[0]);
                mma16816h(s[2 * p + 1], qfr[cc], &kf_h[2]);
                mma16816h(s[2 * p + 1], qfr[cc], &kf_l[2]);
            }
        }

        // ---- online softmax ----
        float mx0 = -INFINITY, mx1 = -INFINITY;
        #pragma unroll
        for (int j = 0; j < 8; j++) {
            mx0 = fmaxf(mx0, fmaxf(s[j][0], s[j][1]));
            mx1 = fmaxf(mx1, fmaxf(s[j][2], s[j][3]));
        }
        mx0 = fmaxf(mx0, __shfl_xor_sync(0xffffffffu, mx0, 1));
        mx0 = fmaxf(mx0, __shfl_xor_sync(0xffffffffu, mx0, 2));
        mx1 = fmaxf(mx1, __shfl_xor_sync(0xffffffffu, mx1, 1));
        mx1 = fmaxf(mx1, __shfl_xor_sync(0xffffffffu, mx1, 2));
        float mn0 = fmaxf(m0, mx0), mn1 = fmaxf(m1, mx1);
        float a0 = __expf(m0 - mn0), a1 = __expf(m1 - mn1);
        m0 = mn0; m1 = mn1;

        uint32_t pfr[4][4];
        float ps0 = 0.f, ps1 = 0.f;
        #pragma unroll
        for (int j = 0; j < 8; j++) {
            float p0 = __expf(s[j][0] - m0);
            float p1 = __expf(s[j][1] - m0);
            float p2 = __expf(s[j][2] - m1);
            float p3 = __expf(s[j][3] - m1);
            ps0 += p0 + p1;
            ps1 += p2 + p3;
            int cc = j >> 1, half = j & 1;
            __half2 pa = __floats2half2_rn(p0, p1);
            __half2 pb = __floats2half2_rn(p2, p3);
            pfr[cc][0 + 2 * half] = *(uint32_t*)&pa;
            pfr[cc][1 + 2 * half] = *(uint32_t*)&pb;
        }
        ps0 += __shfl_xor_sync(0xffffffffu, ps0, 1);
        ps0 += __shfl_xor_sync(0xffffffffu, ps0, 2);
        ps1 += __shfl_xor_sync(0xffffffffu, ps1, 1);
        ps1 += __shfl_xor_sync(0xffffffffu, ps1, 2);
        l0 = l0 * a0 + ps0;
        l1 = l1 * a1 + ps1;

        #pragma unroll
        for (int j = 0; j < 8; j++) {
            o[j][0] *= a0; o[j][1] *= a0;
            o[j][2] *= a1; o[j][3] *= a1;
        }

        // ---- O += P*Vh + P*Vl (2-pass) ----
        #pragma unroll
        for (int cc = 0; cc < 4; cc++) {
            #pragma unroll
            for (int p = 0; p < 4; p++) {
                uint32_t vf_h[4], vf_l[4];
                uint32_t vd = st + 18432 +
                    (uint32_t)(((p * 2 + b_jo) * 8 + lr) * KPITCH + cc * 16 + b_col) * 2;
                ldsm4(vf_h, vd);
                ldsm4(vf_l, vd + 9216);
                mma16816h(o[2 * p],     pfr[cc], &vf_h[0]);
                mma16816h(o[2 * p],     pfr[cc], &vf_l[0]);
                mma16816h(o[2 * p + 1], pfr[cc], &vf_h[2]);
                mma16816h(o[2 * p + 1], pfr[cc], &vf_l[2]);
            }
        }
        __syncthreads();
    }

    // ---- epilogue: O / l, single fp16 into [B,S,H*64] ----
    const int b = bh >> 4;
    const int h = bh & 15;
    float inv0 = 1.0f / l0, inv1 = 1.0f / l1;
    int s0 = q0 + wid * 16 + grp;
    int s1 = s0 + 8;
    #pragma unroll
    for (int j = 0; j < 8; j++) {
        int col = h * HD + j * 8 + 2 * tig;
        size_t off0 = ((size_t)b * SEQ + s0) * HIDDEN + col;
        *(__half2*)(O + off0) = __floats2half2_rn(o[j][0] * inv0, o[j][1] * inv0);
        size_t off1 = ((size_t)b * SEQ + s1) * HIDDEN + col;
        *(__half2*)(O + off1) = __floats2half2_rn(o[j][2] * inv1, o[j][3] * inv1);
    }
}

// ---------------------------------------------------------------------------
extern "C" void kernel_launch(void* const* d_in, const int* in_sizes, int n_in,
                              void* d_out, int out_size)
{
    const float* x     = (const float*)d_in[0];
    const float* W_qkv = (const float*)d_in[1];
    const float* b_qkv = (const float*)d_in[2];
    const float* W_out = (const float*)d_in[3];
    const float* b_out = (const float*)d_in[4];
    float* out = (float*)d_out;

    static __half *pxf = nullptr, *pwqh, *pwql, *pwoh, *pwol;
    static __half *pqf, *pkh, *pkl, *pvth, *pvtl;
    if (!pxf) {
        cudaGetSymbolAddress((void**)&pxf, g_xf);
        cudaGetSymbolAddress((void**)&pwqh, g_wq_h);
        cudaGetSymbolAddress((void**)&pwql, g_wq_l);
        cudaGetSymbolAddress((void**)&pwoh, g_wo_h);
        cudaGetSymbolAddress((void**)&pwol, g_wo_l);
        cudaGetSymbolAddress((void**)&pqf, g_qf);
        cudaGetSymbolAddress((void**)&pkh, g_kh);
        cudaGetSymbolAddress((void**)&pkl, g_kl);
        cudaGetSymbolAddress((void**)&pvth, g_vth);
        cudaGetSymbolAddress((void**)&pvtl, g_vtl);
        cudaFuncSetAttribute(hmma_gemm, cudaFuncAttributeMaxDynamicSharedMemorySize, GEMM_SMEM);
        cudaFuncSetAttribute(attn_hmma, cudaFuncAttributeMaxDynamicSharedMemorySize, ATTN_SMEM);
    }

    const int n4 = MTOT * HIDDEN / 4;

    // 1) cast x -> fp16; transpose+split weights -> fp16 hi/lo
    cast_kernel<<<n4 / 256, 256>>>(x, pxf, n4);
    {
        dim3 g(3 * HIDDEN / 32, HIDDEN / 32);
        tsplit_kernel<<<g, dim3(32, 8)>>>(W_qkv, pwqh, pwql, HIDDEN, 3 * HIDDEN);
    }
    {
        dim3 g(HIDDEN / 32, HIDDEN / 32);
        tsplit_kernel<<<g, dim3(32, 8)>>>(W_out, pwoh, pwol, HIDDEN, HIDDEN);
    }

    // 2) QKV projection (fp16 2-pass HMMA) -> Q/K/V fp16
    {
        dim3 g(3 * HIDDEN / 128, MTOT / 128);   // (24, 64)
        hmma_gemm<<<g, 128, GEMM_SMEM>>>(pxf, pwqh, pwql, b_qkv, nullptr,
                                         pqf, pkh, pkl, pvth, pvtl,
                                         MTOT, 3 * HIDDEN, HIDDEN, 1);
    }

    // 3) fp16 flash attention -> fp16 activations (reuse g_xf)
    {
        dim3 g(SEQ / 128, BATCH * HEADS);       // (16, 64)
        attn_hmma<<<g, 256, ATTN_SMEM>>>(pqf, pkh, pkl, pvth, pvtl, pxf);
    }

    // 4) output projection (fp16 2-pass HMMA) -> d_out
    {
        dim3 g(HIDDEN / 128, MTOT / 128);       // (8, 64)
        hmma_gemm<<<g, 128, GEMM_SMEM>>>(pxf, pwoh, pwol, b_out, out,
                                         nullptr, nullptr, nullptr, nullptr, nullptr,
                                         MTOT, HIDDEN, HIDDEN, 0);
    }
}